// round 7
// baseline (speedup 1.0000x reference)
#include <cuda_runtime.h>
#include <cuda_fp16.h>
#include <cstdint>
#include <math.h>

// Problem dims
#define BB   4
#define SS   1024
#define DD   1024
#define HH   16
#define DH   64
#define RR   64
#define DFFN 4096
#define NTOK (BB*SS)       // 4096
#define KSEL 204           // int(1024*0.2)

// ---------------- scratch (device globals) ----------------
__device__ __half g_hw_in[(long)3 * DD * DD];
__device__ __half g_hw_out[(long)DD * DD];
__device__ __half g_hw_Vp[(long)DD * DD];
__device__ __half g_hw_f1[(long)DFFN * DD];
__device__ __half g_hw_f2[(long)DD * DFFN];
__device__ __half g_hw_QK[2 * RR * DD];          // packed [Qp_w; Kp_w]
__device__ float  g_bias_QK[2 * RR];
__device__ __half g_src_h[(long)NTOK * DD];
__device__ __half g_qkv_h[(long)NTOK * 3 * DD];
__device__ __half g_ctx_h[(long)NTOK * DD];
__device__ __half g_QKlr_h[(long)NTOK * 2 * RR];
__device__ __half g_Vlr_h[(long)NTOK * DD];
__device__ __half g_Vt_h[(long)NTOK * DD];
__device__ __half g_Ph[(long)BB * SS * SS];
__device__ __half g_x_h[(long)NTOK * DD];
__device__ __half g_h1_h[(long)NTOK * DFFN];
__device__ float g_P[(long)BB * SS * SS];
__device__ float g_dense[(long)NTOK * DD];
__device__ float g_sparse[(long)NTOK * DD];
__device__ float g_x[(long)NTOK * DD];
__device__ float g_ff[(long)NTOK * DD];

// ======================= helpers =======================
__device__ __forceinline__ uint32_t smem_u32(const void* p) {
    uint32_t a;
    asm("{ .reg .u64 t; cvta.to.shared.u64 t, %1; cvt.u32.u64 %0, t; }" : "=r"(a) : "l"(p));
    return a;
}
__device__ __forceinline__ void cp16(uint32_t saddr, const void* g) {
    asm volatile("cp.async.ca.shared.global [%0], [%1], 16;"
                 :: "r"(saddr), "l"(g) : "memory");
}
#define CP_COMMIT() asm volatile("cp.async.commit_group;" ::: "memory")
#define CP_WAIT2()  asm volatile("cp.async.wait_group 2;" ::: "memory")
#define CP_WAIT1()  asm volatile("cp.async.wait_group 1;" ::: "memory")
#define CP_WAIT0()  asm volatile("cp.async.wait_group 0;" ::: "memory")

__device__ __forceinline__ void mma_f16(float* c, const uint32_t* a, const uint32_t* b) {
    asm volatile(
        "mma.sync.aligned.m16n8k16.row.col.f32.f16.f16.f32 "
        "{%0,%1,%2,%3}, {%4,%5,%6,%7}, {%8,%9}, {%0,%1,%2,%3};"
        : "+f"(c[0]), "+f"(c[1]), "+f"(c[2]), "+f"(c[3])
        : "r"(a[0]), "r"(a[1]), "r"(a[2]), "r"(a[3]), "r"(b[0]), "r"(b[1]));
}
__device__ __forceinline__ void ldsm_x4(uint32_t* r, uint32_t saddr) {
    asm volatile("ldmatrix.sync.aligned.m8n8.x4.shared.b16 {%0,%1,%2,%3}, [%4];"
                 : "=r"(r[0]), "=r"(r[1]), "=r"(r[2]), "=r"(r[3]) : "r"(saddr));
}
__device__ __forceinline__ uint32_t h2u(float x, float y) {
    __half2 h = __floats2half2_rn(x, y);
    return *(uint32_t*)&h;
}

// ======================= fused converter =======================
__global__ __launch_bounds__(256) void convert_all(
    const float* in_w, const float* outp_w, const float* Vp_w,
    const float* ff1_w, const float* ff2_w, const float* src,
    const float* Qp_w, const float* Kp_w, const float* Qp_b, const float* Kp_b,
    __half* hw_in, __half* hw_out, __half* hw_Vp, __half* hw_f1, __half* hw_f2,
    __half* src_h, __half* hw_QK, float* bias_QK)
{
    const int bid = blockIdx.x, t = threadIdx.x;
    if (bid == 17536) {
        if (t < RR) bias_QK[t] = Qp_b[t];
        else if (t < 2 * RR) bias_QK[t] = Kp_b[t - RR];
        return;
    }
    const float* in; __half* out; long off;
    if      (bid < 3072)  { in = in_w;  out = hw_in;  off = (long)bid * 1024; }
    else if (bid < 4096)  { in = outp_w; out = hw_out; off = (long)(bid - 3072) * 1024; }
    else if (bid < 5120)  { in = Vp_w;  out = hw_Vp;  off = (long)(bid - 4096) * 1024; }
    else if (bid < 9216)  { in = ff1_w; out = hw_f1;  off = (long)(bid - 5120) * 1024; }
    else if (bid < 13312) { in = ff2_w; out = hw_f2;  off = (long)(bid - 9216) * 1024; }
    else if (bid < 17408) { in = src;   out = src_h;  off = (long)(bid - 13312) * 1024; }
    else if (bid < 17472) { in = Qp_w;  out = hw_QK;  off = (long)(bid - 17408) * 1024; }
    else                  { in = Kp_w;  out = hw_QK + (long)RR * DD; off = (long)(bid - 17472) * 1024; }
    long i = off + t * 4;
    float4 v = *(const float4*)(in + i);
    *(__half2*)(out + i) = __floats2half2_rn(v.x, v.y);
    *(__half2*)(out + i + 2) = __floats2half2_rn(v.z, v.w);
}

// ======================= fp16 warp-MMA GEMM (big warp tile) =======================
// C = alpha * A(MxK, lda) * B^T(NxK, ldb) + bias
// CTA tile 256x128x32h; 8 warps (4x2); warp tile 64x64; 3-stage cp.async; ldmatrix x4.
#define BM 256
#define BN 128
#define BKH 32     // halves per K chunk (two k16 sub-chunks)
#define KSTRH 20   // b32 row stride (16 data + 4 pad)
#define A_B32 (BM * KSTRH)        // 5120
#define STG_B32 (A_B32 + BN * KSTRH)  // 7680
#define GEMM_SMEM (3 * STG_B32 * 4)   // 92160 B

__global__ __launch_bounds__(256) void hgemm_nt(
    const __half* __restrict__ A, const __half* __restrict__ B,
    const float* __restrict__ bias, void* __restrict__ Cout,
    int N, int K, int lda, int ldb,
    long sA, long sB, long sC, float alpha, int relu, int out_half)
{
    extern __shared__ uint32_t gsm[];

    A += (long)blockIdx.z * sA;
    B += (long)blockIdx.z * sB;

    const int t = threadIdx.x;
    const int wid = t >> 5, l = t & 31;
    const int wm = wid >> 1, wn = wid & 1;     // 4 x 2 warp grid
    const int mbase = wm * 64, nbase = wn * 64;
    const int qr = l >> 2, qc = l & 3;
    const int row0 = blockIdx.y * BM, col0 = blockIdx.x * BN;

    const uint32_t s0 = smem_u32(gsm);

    const int lr = t >> 2;            // 0..63
    const int lc4 = (t & 3) * 4;      // b32 col

    // ldmatrix lane addresses (stage-0 byte offsets)
    // A x4: m0 rows0-7 c0 | m1 rows8-15 c0 | m2 rows0-7 c4 | m3 rows8-15 c4
    const uint32_t a_lm = s0 + (uint32_t)(((mbase + (l & 15)) * KSTRH + (l >> 4) * 4) * 4);
    // B x4: m0 n0-7 c0 | m1 n0-7 c4 | m2 n8-15 c0 | m3 n8-15 c4  (two n8 frag pairs)
    const uint32_t b_lm = s0 + (uint32_t)((A_B32 +
        (nbase + (l & 7) + ((l >> 4) << 3)) * KSTRH + (((l >> 3) & 1) * 4)) * 4);

    float acc[4][8][4];
#pragma unroll
    for (int i = 0; i < 4; i++)
#pragma unroll
        for (int j = 0; j < 8; j++)
#pragma unroll
            for (int q = 0; q < 4; q++) acc[i][j][q] = 0.f;

    const int nc = K / BKH;

    auto prefetch = [&](int cc) {
        const int st = cc % 3;
        const int k0 = cc * BKH;
        const uint32_t sAs = s0 + st * STG_B32 * 4;
        const uint32_t sBs = sAs + A_B32 * 4;
#pragma unroll
        for (int j = 0; j < 4; j++) {
            int m = lr + j * 64;
            cp16(sAs + (m * KSTRH + lc4) * 4, &A[(long)(row0 + m) * lda + k0 + lc4 * 2]);
        }
#pragma unroll
        for (int j = 0; j < 2; j++) {
            int n = lr + j * 64;
            cp16(sBs + (n * KSTRH + lc4) * 4, &B[(long)(col0 + n) * ldb + k0 + lc4 * 2]);
        }
        CP_COMMIT();
    };

    prefetch(0);
    if (nc > 1) prefetch(1);

    for (int c = 0; c < nc; c++) {
        if (c + 2 < nc) { prefetch(c + 2); CP_WAIT2(); }
        else if (c + 1 < nc) { CP_WAIT1(); }
        else { CP_WAIT0(); }
        __syncthreads();

        const uint32_t stoff = (uint32_t)((c % 3) * STG_B32 * 4);
#pragma unroll
        for (int kk = 0; kk < 2; kk++) {
            const uint32_t koff = stoff + kk * 8 * 4;
            uint32_t af[4][4], bf[4][4];
#pragma unroll
            for (int mt = 0; mt < 4; mt++)
                ldsm_x4(af[mt], a_lm + koff + mt * 16 * KSTRH * 4);
#pragma unroll
            for (int np = 0; np < 4; np++)
                ldsm_x4(bf[np], b_lm + koff + np * 16 * KSTRH * 4);
#pragma unroll
            for (int mt = 0; mt < 4; mt++) {
#pragma unroll
                for (int nt = 0; nt < 8; nt++)
                    mma_f16(acc[mt][nt], af[mt], &bf[nt >> 1][(nt & 1) * 2]);
            }
        }
        __syncthreads();
    }

    // ---- epilogue ----
#pragma unroll
    for (int mt = 0; mt < 4; mt++) {
        const int r = row0 + mbase + mt * 16 + qr;
#pragma unroll
        for (int nt = 0; nt < 8; nt++) {
            const int cc = col0 + nbase + nt * 8 + qc * 2;
            float b0 = 0.f, b1 = 0.f;
            if (bias) { b0 = bias[cc]; b1 = bias[cc + 1]; }
            float v0 = acc[mt][nt][0] * alpha + b0;
            float v1 = acc[mt][nt][1] * alpha + b1;
            float v2 = acc[mt][nt][2] * alpha + b0;
            float v3 = acc[mt][nt][3] * alpha + b1;
            if (relu) {
                v0 = fmaxf(v0, 0.f); v1 = fmaxf(v1, 0.f);
                v2 = fmaxf(v2, 0.f); v3 = fmaxf(v3, 0.f);
            }
            if (out_half) {
                __half* C = (__half*)Cout + blockIdx.z * sC;
                *(__half2*)&C[(long)r * N + cc] = __floats2half2_rn(v0, v1);
                *(__half2*)&C[(long)(r + 8) * N + cc] = __floats2half2_rn(v2, v3);
            } else {
                float* C = (float*)Cout + blockIdx.z * sC;
                float2 p0 = {v0, v1}, p1 = {v2, v3};
                *(float2*)&C[(long)r * N + cc] = p0;
                *(float2*)&C[(long)(r + 8) * N + cc] = p1;
            }
        }
    }
}

// ======================= half transpose =======================
__global__ __launch_bounds__(256) void transpose_h_kernel(const __half* __restrict__ V,
                                                          __half* __restrict__ Vt)
{
    __shared__ __half tile[32][33];
    const __half* Vb = V + (long)blockIdx.z * SS * DD;
    __half* Vtb = Vt + (long)blockIdx.z * SS * DD;
    const int s0 = blockIdx.x * 32, d0 = blockIdx.y * 32;
    const int tx = threadIdx.x & 31, ty0 = threadIdx.x >> 5;
#pragma unroll
    for (int i = 0; i < 4; i++) {
        int ty = ty0 + i * 8;
        tile[ty][tx] = Vb[(long)(s0 + ty) * DD + d0 + tx];
    }
    __syncthreads();
#pragma unroll
    for (int i = 0; i < 4; i++) {
        int ty = ty0 + i * 8;
        Vtb[(long)(d0 + ty) * SS + s0 + tx] = tile[tx][ty];
    }
}

// ======================= fp16 tensor-core flash attention =======================
#define FSTR 36

__global__ __launch_bounds__(256) void flash_attn_kernel(const __half* __restrict__ qkv,
                                                         __half* __restrict__ ctx)
{
    __shared__ uint32_t ps[128 * FSTR];
    __shared__ uint32_t ks[64 * FSTR];
    __shared__ uint32_t vs[64 * FSTR];
    __half* vs_h = (__half*)vs;

    const int t = threadIdx.x, w = t >> 5, l = t & 31;
    const int qr = l >> 2, qc = l & 3;
    const int q0 = blockIdx.x * 128, h = blockIdx.y, b = blockIdx.z;
    const int wr = w * 16;

    const __half* Qg = qkv + (long)(b * SS + q0) * (3 * DD) + h * DH;
    const __half* Kg = qkv + (long)(b * SS) * (3 * DD) + DD + h * DH;
    const __half* Vg = qkv + (long)(b * SS) * (3 * DD) + 2 * DD + h * DH;

#pragma unroll
    for (int i = 0; i < 4; i++) {
        int idx = t + i * 256;
        int r = idx >> 3, c16 = idx & 7;
        float4 v = *(const float4*)(Qg + (long)r * (3 * DD) + c16 * 8);
        *(float4*)&ps[r * FSTR + c16 * 4] = v;
    }
    __syncthreads();
    uint32_t qa[4][4];
#pragma unroll
    for (int k = 0; k < 4; k++) {
        qa[k][0] = ps[(wr + qr) * FSTR + k * 8 + qc];
        qa[k][1] = ps[(wr + qr + 8) * FSTR + k * 8 + qc];
        qa[k][2] = ps[(wr + qr) * FSTR + k * 8 + qc + 4];
        qa[k][3] = ps[(wr + qr + 8) * FSTR + k * 8 + qc + 4];
    }
    __syncthreads();

    float m0 = -1e30f, m1 = -1e30f, l0 = 0.f, l1 = 0.f;
    float o[8][4];
#pragma unroll
    for (int n = 0; n < 8; n++)
#pragma unroll
        for (int i = 0; i < 4; i++) o[n][i] = 0.f;

    for (int kt = 0; kt < SS; kt += 64) {
#pragma unroll
        for (int i = 0; i < 2; i++) {
            int idx = t + i * 256;
            int r = idx >> 3, c16 = idx & 7;
            float4 kv = *(const float4*)(Kg + (long)(kt + r) * (3 * DD) + c16 * 8);
            *(float4*)&ks[r * FSTR + c16 * 4] = kv;
            float4 vv = *(const float4*)(Vg + (long)(kt + r) * (3 * DD) + c16 * 8);
            const __half* vh = (const __half*)&vv;
#pragma unroll
            for (int j = 0; j < 8; j++)
                vs_h[(c16 * 8 + j) * (2 * FSTR) + r] = vh[j];
        }
        __syncthreads();

        float sa[8][4];
#pragma unroll
        for (int n = 0; n < 8; n++)
#pragma unroll
            for (int i = 0; i < 4; i++) sa[n][i] = 0.f;
#pragma unroll
        for (int k = 0; k < 4; k++) {
#pragma unroll
            for (int n = 0; n < 8; n++) {
                uint32_t bf[2];
                bf[0] = ks[(n * 8 + qr) * FSTR + k * 8 + qc];
                bf[1] = ks[(n * 8 + qr) * FSTR + k * 8 + qc + 4];
                mma_f16(sa[n], qa[k], bf);
            }
        }

        float rm0 = -1e30f, rm1 = -1e30f;
#pragma unroll
        for (int n = 0; n < 8; n++) {
            sa[n][0] *= 0.125f; sa[n][1] *= 0.125f;
            sa[n][2] *= 0.125f; sa[n][3] *= 0.125f;
            rm0 = fmaxf(rm0, fmaxf(sa[n][0], sa[n][1]));
            rm1 = fmaxf(rm1, fmaxf(sa[n][2], sa[n][3]));
        }
        rm0 = fmaxf(rm0, __shfl_xor_sync(0xffffffffu, rm0, 1));
        rm0 = fmaxf(rm0, __shfl_xor_sync(0xffffffffu, rm0, 2));
        rm1 = fmaxf(rm1, __shfl_xor_sync(0xffffffffu, rm1, 1));
        rm1 = fmaxf(rm1, __shfl_xor_sync(0xffffffffu, rm1, 2));

        const float nm0 = fmaxf(m0, rm0), nm1 = fmaxf(m1, rm1);
        const float c0 = __expf(m0 - nm0), c1 = __expf(m1 - nm1);
        float rs0 = 0.f, rs1 = 0.f;
#pragma unroll
        for (int n = 0; n < 8; n++) {
            float p0 = __expf(sa[n][0] - nm0);
            float p1 = __expf(sa[n][1] - nm0);
            float p2 = __expf(sa[n][2] - nm1);
            float p3 = __expf(sa[n][3] - nm1);
            rs0 += p0 + p1; rs1 += p2 + p3;
            ps[(wr + qr) * FSTR + n * 4 + qc] = h2u(p0, p1);
            ps[(wr + qr + 8) * FSTR + n * 4 + qc] = h2u(p2, p3);
            o[n][0] *= c0; o[n][1] *= c0; o[n][2] *= c1; o[n][3] *= c1;
        }
        rs0 += __shfl_xor_sync(0xffffffffu, rs0, 1);
        rs0 += __shfl_xor_sync(0xffffffffu, rs0, 2);
        rs1 += __shfl_xor_sync(0xffffffffu, rs1, 1);
        rs1 += __shfl_xor_sync(0xffffffffu, rs1, 2);
        l0 = l0 * c0 + rs0; l1 = l1 * c1 + rs1;
        m0 = nm0; m1 = nm1;

        __syncwarp();

#pragma unroll
        for (int k = 0; k < 4; k++) {
            uint32_t pa[4];
            pa[0] = ps[(wr + qr) * FSTR + k * 8 + qc];
            pa[1] = ps[(wr + qr + 8) * FSTR + k * 8 + qc];
            pa[2] = ps[(wr + qr) * FSTR + k * 8 + qc + 4];
            pa[3] = ps[(wr + qr + 8) * FSTR + k * 8 + qc + 4];
#pragma unroll
            for (int n = 0; n < 8; n++) {
                uint32_t bf[2];
                bf[0] = vs[(n * 8 + qr) * FSTR + k * 8 + qc];
                bf[1] = vs[(n * 8 + qr) * FSTR + k * 8 + qc + 4];
                mma_f16(o[n], pa, bf);
            }
        }
        __syncthreads();
    }

    const float i0 = 1.f / l0, i1 = 1.f / l1;
    __half* Og = ctx + (long)(b * SS + q0 + wr) * DD + h * DH;
#pragma unroll
    for (int n = 0; n < 8; n++) {
        *(__half2*)&Og[(long)qr * DD + n * 8 + 2 * qc] = __floats2half2_rn(o[n][0] * i0, o[n][1] * i0);
        *(__half2*)&Og[(long)(qr + 8) * DD + n * 8 + 2 * qc] = __floats2half2_rn(o[n][2] * i1, o[n][3] * i1);
    }
}

// ======================= radix-select top-k + masked softmax -> half P =======================
__global__ __launch_bounds__(256) void topk_softmax_kernel(const float* __restrict__ P,
                                                           __half* __restrict__ Ph)
{
    const long base = (long)blockIdx.x * SS;
    __shared__ float vals[SS];
    __shared__ unsigned keys[SS];
    __shared__ unsigned hist[256];
    __shared__ float redA[8], redB[8];
    __shared__ unsigned s_prefix;
    __shared__ int s_need;

    const int t = threadIdx.x;
    const int w = t >> 5, lane = t & 31;

    float lmax = -1e30f;
#pragma unroll
    for (int i = 0; i < 4; i++) {
        float v = P[base + t + i * 256];
        vals[t + i * 256] = v;
        unsigned u = __float_as_uint(v);
        u ^= (u >> 31) ? 0xFFFFFFFFu : 0x80000000u;
        keys[t + i * 256] = u;
        lmax = fmaxf(lmax, v);
    }
#pragma unroll
    for (int o = 16; o > 0; o >>= 1)
        lmax = fmaxf(lmax, __shfl_xor_sync(0xffffffffu, lmax, o));
    if (lane == 0) redA[w] = lmax;
    __syncthreads();
    float mx = redA[0];
#pragma unroll
    for (int i = 1; i < 8; i++) mx = fmaxf(mx, redA[i]);

    unsigned prefix = 0;
    int need = KSEL;
#pragma unroll
    for (int pass = 0; pass < 4; pass++) {
        const int shift = 24 - 8 * pass;
        const unsigned hmask = pass ? (0xFFFFFFFFu << (shift + 8)) : 0u;
        hist[t] = 0;
        __syncthreads();
#pragma unroll
        for (int i = 0; i < 4; i++) {
            unsigned u = keys[t + i * 256];
            if ((u & hmask) == prefix)
                atomicAdd(&hist[(u >> shift) & 0xFFu], 1u);
        }
        __syncthreads();
        if (t == 0) {
            int cum = 0, bsel = 0;
            for (int bbin = 255; bbin >= 0; bbin--) {
                int hh = (int)hist[bbin];
                if (cum + hh >= need) { bsel = bbin; break; }
                cum += hh;
            }
            s_prefix = prefix | ((unsigned)bsel << shift);
            s_need = need - cum;
        }
        __syncthreads();
        prefix = s_prefix;
        need = s_need;
        __syncthreads();
    }
    const unsigned thr = prefix;

    float e[4];
    float sk = 0.f, sf = 0.f;
#pragma unroll
    for (int i = 0; i < 4; i++) {
        float v = vals[t + i * 256];
        float ef = __expf(v - mx);
        bool kp = keys[t + i * 256] >= thr;
        e[i] = kp ? ef : 0.f;
        sk += e[i];
        sf += ef;
    }
#pragma unroll
    for (int o = 16; o > 0; o >>= 1) {
        sk += __shfl_xor_sync(0xffffffffu, sk, o);
        sf += __shfl_xor_sync(0xffffffffu, sf, o);
    }
    if (lane == 0) { redA[w] = sk; redB[w] = sf; }
    __syncthreads();
    float tk = 0.f, tf = 0.f;
#pragma unroll
    for (int i = 0; i < 8; i++) { tk += redA[i]; tf += redB[i]; }
    const float inv = 1.f / (tk + 1e-9f * tf);
#pragma unroll
    for (int i = 0; i < 4; i++)
        Ph[base + t + i * 256] = __float2half(e[i] * inv);
}

// ======================= fuse + residual + LN1 =======================
__global__ __launch_bounds__(256) void fuse_ln1_kernel(
    const float* __restrict__ src, const float* __restrict__ dense,
    const float* __restrict__ sparse, const float* __restrict__ lam,
    const float* __restrict__ g, const float* __restrict__ bb,
    float* __restrict__ x, __half* __restrict__ xh)
{
    const long row = (long)blockIdx.x * DD;
    __shared__ float buf[DD];
    __shared__ float r1[8], r2[8];
    const float sig = 1.f / (1.f + __expf(-lam[0]));
    const float osig = 1.f - sig;

    float s1 = 0.f, s2 = 0.f;
    for (int d = threadIdx.x; d < DD; d += 256) {
        float v = src[row + d] + sig * dense[row + d] + osig * sparse[row + d];
        buf[d] = v; s1 += v; s2 += v * v;
    }
#pragma unroll
    for (int o = 16; o > 0; o >>= 1) {
        s1 += __shfl_xor_sync(0xffffffffu, s1, o);
        s2 += __shfl_xor_sync(0xffffffffu, s2, o);
    }
    const int w = threadIdx.x >> 5, lane = threadIdx.x & 31;
    if (lane == 0) { r1[w] = s1; r2[w] = s2; }
    __syncthreads();
    if (threadIdx.x == 0) {
        float a = 0.f, c = 0.f;
        for (int i = 0; i < 8; i++) { a += r1[i]; c += r2[i]; }
        r1[0] = a; r2[0] = c;
    }
    __syncthreads();
    const float mean = r1[0] * (1.f / DD);
    const float var = r2[0] * (1.f / DD) - mean * mean;
    const float rstd = rsqrtf(var + 1e-5f);
    for (int d = threadIdx.x; d < DD; d += 256) {
        float v = (buf[d] - mean) * rstd * g[d] + bb[d];
        x[row + d] = v;
        xh[row + d] = __float2half(v);
    }
}

// ======================= residual + LN2 -> out =======================
__global__ __launch_bounds__(256) void ln2_kernel(
    const float* __restrict__ x, const float* __restrict__ ff,
    const float* __restrict__ g, const float* __restrict__ bb,
    float* __restrict__ out)
{
    const long row = (long)blockIdx.x * DD;
    __shared__ float buf[DD];
    __shared__ float r1[8], r2[8];

    float s1 = 0.f, s2 = 0.f;
    for (int d = threadIdx.x; d < DD; d += 256) {
        float v = x[row + d] + ff[row + d];
        buf[d] = v; s1 += v; s2 += v * v;
    }
#pragma unroll
    for (int o = 16; o > 0; o >>= 1) {
        s1 += __shfl_xor_sync(0xffffffffu, s1, o);
        s2 += __shfl_xor_sync(0xffffffffu, s2, o);
    }
    const int w = threadIdx.x >> 5, lane = threadIdx.x & 31;
    if (lane == 0) { r1[w] = s1; r2[w] = s2; }
    __syncthreads();
    if (threadIdx.x == 0) {
        float a = 0.f, c = 0.f;
        for (int i = 0; i < 8; i++) { a += r1[i]; c += r2[i]; }
        r1[0] = a; r2[0] = c;
    }
    __syncthreads();
    const float mean = r1[0] * (1.f / DD);
    const float var = r2[0] * (1.f / DD) - mean * mean;
    const float rstd = rsqrtf(var + 1e-5f);
    for (int d = threadIdx.x; d < DD; d += 256)
        out[row + d] = (buf[d] - mean) * rstd * g[d] + bb[d];
}

// ======================= launch =======================
extern "C" void kernel_launch(void* const* d_in, const int* in_sizes, int n_in,
                              void* d_out, int out_size)
{
    (void)in_sizes; (void)n_in; (void)out_size;
    const float* src    = (const float*)d_in[0];
    const float* in_w   = (const float*)d_in[1];
    const float* in_b   = (const float*)d_in[2];
    const float* outp_w = (const float*)d_in[3];
    const float* outp_b = (const float*)d_in[4];
    const float* Qp_w   = (const float*)d_in[5];
    const float* Qp_b   = (const float*)d_in[6];
    const float* Kp_w   = (const float*)d_in[7];
    const float* Kp_b   = (const float*)d_in[8];
    const float* Vp_w   = (const float*)d_in[9];
    const float* Vp_b   = (const float*)d_in[10];
    const float* lam    = (const float*)d_in[11];
    const float* ff1_w  = (const float*)d_in[12];
    const float* ff1_b  = (const float*)d_in[13];
    const float* ff2_w  = (const float*)d_in[14];
    const float* ff2_b  = (const float*)d_in[15];
    const float* ln1_g  = (const float*)d_in[16];
    const float* ln1_b  = (const float*)d_in[17];
    const float* ln2_g  = (const float*)d_in[18];
    const float* ln2_b  = (const float*)d_in[19];
    float* out = (float*)d_out;

    __half *hw_in, *hw_out, *hw_Vp, *hw_f1, *hw_f2, *hw_QK;
    __half *src_h, *qkv_h, *ctx_h, *QKlr_h, *Vlr_h, *Vt_h, *Ph, *x_h, *h1_h;
    float *bias_QK, *P, *dense, *sparse, *x, *ff;
    cudaGetSymbolAddress((void**)&hw_in,   g_hw_in);
    cudaGetSymbolAddress((void**)&hw_out,  g_hw_out);
    cudaGetSymbolAddress((void**)&hw_Vp,   g_hw_Vp);
    cudaGetSymbolAddress((void**)&hw_f1,   g_hw_f1);
    cudaGetSymbolAddress((void**)&hw_f2,   g_hw_f2);
    cudaGetSymbolAddress((void**)&hw_QK,   g_hw_QK);
    cudaGetSymbolAddress((void**)&bias_QK, g_bias_QK);
    cudaGetSymbolAddress((void**)&src_h,   g_src_h);
    cudaGetSymbolAddress((void**)&qkv_h,   g_qkv_h);
    cudaGetSymbolAddress((void**)&ctx_h,   g_ctx_h);
    cudaGetSymbolAddress((void**)&QKlr_h,  g_QKlr_h);
    cudaGetSymbolAddress((void**)&Vlr_h,   g_Vlr_h);
    cudaGetSymbolAddress((void**)&Vt_h,    g_Vt_h);
    cudaGetSymbolAddress((void**)&Ph,      g_Ph);
    cudaGetSymbolAddress((void**)&x_h,     g_x_h);
    cudaGetSymbolAddress((void**)&h1_h,    g_h1_h);
    cudaGetSymbolAddress((void**)&P,       g_P);
    cudaGetSymbolAddress((void**)&dense,   g_dense);
    cudaGetSymbolAddress((void**)&sparse,  g_sparse);
    cudaGetSymbolAddress((void**)&x,       g_x);
    cudaGetSymbolAddress((void**)&ff,      g_ff);

    cudaFuncSetAttribute(hgemm_nt, cudaFuncAttributeMaxDynamicSharedMemorySize, GEMM_SMEM);

    // 0. fused conversion
    convert_all<<<17537, 256>>>(in_w, outp_w, Vp_w, ff1_w, ff2_w, src,
                                Qp_w, Kp_w, Qp_b, Kp_b,
                                hw_in, hw_out, hw_Vp, hw_f1, hw_f2,
                                src_h, hw_QK, bias_QK);

    // 1. qkv = src @ in_proj^T + b -> half
    hgemm_nt<<<dim3(3 * DD / BN, NTOK / BM), 256, GEMM_SMEM>>>(
        src_h, hw_in, in_b, qkv_h, 3 * DD, DD, DD, DD, 0, 0, 0, 1.f, 0, 1);
    // 2. dense attention -> half ctx
    flash_attn_kernel<<<dim3(SS / 128, HH, BB), 256>>>(qkv_h, ctx_h);
    // 3. dense = ctx @ out_proj^T + b -> f32
    hgemm_nt<<<dim3(DD / BN, NTOK / BM), 256, GEMM_SMEM>>>(
        ctx_h, hw_out, outp_b, dense, DD, DD, DD, DD, 0, 0, 0, 1.f, 0, 0);
    // 4. QKlr = src @ [Qp;Kp]^T + b -> half [4096,128]
    hgemm_nt<<<dim3(1, NTOK / BM), 256, GEMM_SMEM>>>(
        src_h, hw_QK, bias_QK, QKlr_h, 2 * RR, DD, DD, DD, 0, 0, 0, 1.f, 0, 1);
    // 5. Vlr = src @ Vp^T + b -> half
    hgemm_nt<<<dim3(DD / BN, NTOK / BM), 256, GEMM_SMEM>>>(
        src_h, hw_Vp, Vp_b, Vlr_h, DD, DD, DD, DD, 0, 0, 0, 1.f, 0, 1);
    // 6. P = (Q @ K^T)/sqrt(R) per batch -> f32
    hgemm_nt<<<dim3(SS / BN, SS / BM, BB), 256, GEMM_SMEM>>>(
        QKlr_h, QKlr_h + RR, nullptr, P, SS, RR, 2 * RR, 2 * RR,
        (long)SS * 2 * RR, (long)SS * 2 * RR, (long)SS * SS, 0.125f, 0, 0);
    // 7. radix top-k + masked softmax -> half P
    topk_softmax_kernel<<<NTOK, 256>>>(P, Ph);
    // 8. Vt = V^T per batch
    transpose_h_kernel<<<dim3(SS / 32, DD / 32, BB), 256>>>(Vlr_h, Vt_h);
    // 9. sparse = P @ Vt^T per batch -> f32
    hgemm_nt<<<dim3(DD / BN, SS / BM, BB), 256, GEMM_SMEM>>>(
        Ph, Vt_h, nullptr, sparse, DD, SS, SS, SS,
        (long)SS * SS, (long)SS * DD, (long)SS * DD, 1.f, 0, 0);
    // 10. x = LN1(...) -> f32 + half
    fuse_ln1_kernel<<<NTOK, 256>>>(src, dense, sparse, lam, ln1_g, ln1_b, x, x_h);
    // 11. h1 = relu(x @ ff1^T + b) -> half
    hgemm_nt<<<dim3(DFFN / BN, NTOK / BM), 256, GEMM_SMEM>>>(
        x_h, hw_f1, ff1_b, h1_h, DFFN, DD, DD, DD, 0, 0, 0, 1.f, 1, 1);
    // 12. ff = h1 @ ff2^T + b -> f32
    hgemm_nt<<<dim3(DD / BN, NTOK / BM), 256, GEMM_SMEM>>>(
        h1_h, hw_f2, ff2_b, ff, DD, DFFN, DFFN, DFFN, 0, 0, 0, 1.f, 0, 0);
    // 13. out = LN2(x + ff)
    ln2_kernel<<<NTOK, 256>>>(x, ff, ln2_g, ln2_b, out);
}